// round 2
// baseline (speedup 1.0000x reference)
#include <cuda_runtime.h>
#include <cuda_bf16.h>
#include <math.h>

// ---------------------------------------------------------------------------
// Problem constants
//   x      [256, 64, 2048]  fp32
//   W_qkv  [6144, 2048]     fp32   (qkv = x @ W_qkv^T + b_qkv)
//   b_qkv  [6144]
//   W_out  [2048, 2048]     fp32   (out = att @ W_out^T + b_out)
//   b_out  [2048]
//   H = 16 heads, hd = 128, S = 64, B = 256, tokens = 16384
//   scores scaled by 1/sqrt(d_model) = 1/sqrt(2048)
//   softmax over the QUERY axis (axis=-2) per key column, causal mask k<=q
// ---------------------------------------------------------------------------

#define TOK      16384
#define DMODEL   2048
#define E3       6144
#define NHEAD    16
#define HD       128
#define SEQ      64
#define NBATCH   256

// Scratch (device globals: allocation rules forbid cudaMalloc)
__device__ float g_qkv[(size_t)TOK * E3];     // 402 MB
__device__ float g_att[(size_t)TOK * DMODEL]; // 134 MB

// ---------------------------------------------------------------------------
// NT SGEMM: C[M,N] = A[M,K] @ B[N,K]^T + bias[N]
// A row-major [M,K], B row-major [N,K] (both K-contiguous).
// 128x128 tile, BK=8, 256 threads, 8x8 per-thread microtile.
// ---------------------------------------------------------------------------
__global__ void __launch_bounds__(256, 2)
gemm_nt(const float* __restrict__ A, const float* __restrict__ Bm,
        const float* __restrict__ bias, float* __restrict__ C,
        int M, int N, int K)
{
    __shared__ float As[8][128];
    __shared__ float Bs[8][128];

    const int bm  = blockIdx.y * 128;
    const int bn  = blockIdx.x * 128;
    const int tid = threadIdx.x;

    // gmem load mapping: each thread loads one float4 of A and one of B per k-tile
    const int lr = tid >> 1;          // row within tile: 0..127
    const int lk = (tid & 1) * 4;     // k offset: 0 or 4
    const float* Ag = A  + (size_t)(bm + lr) * K + lk;
    const float* Bg = Bm + (size_t)(bn + lr) * K + lk;

    // compute mapping: 16x16 thread grid, 8x8 micro tile
    const int tr = (tid >> 4) * 8;
    const int tc = (tid & 15) * 8;

    float acc[8][8];
#pragma unroll
    for (int i = 0; i < 8; i++)
#pragma unroll
        for (int j = 0; j < 8; j++) acc[i][j] = 0.0f;

    for (int k0 = 0; k0 < K; k0 += 8) {
        float4 a = *(const float4*)(Ag + k0);
        float4 b = *(const float4*)(Bg + k0);
        As[lk + 0][lr] = a.x; As[lk + 1][lr] = a.y;
        As[lk + 2][lr] = a.z; As[lk + 3][lr] = a.w;
        Bs[lk + 0][lr] = b.x; Bs[lk + 1][lr] = b.y;
        Bs[lk + 2][lr] = b.z; Bs[lk + 3][lr] = b.w;
        __syncthreads();

#pragma unroll
        for (int kk = 0; kk < 8; kk++) {
            float ra[8], rb[8];
            *(float4*)(ra)     = *(const float4*)&As[kk][tr];
            *(float4*)(ra + 4) = *(const float4*)&As[kk][tr + 4];
            *(float4*)(rb)     = *(const float4*)&Bs[kk][tc];
            *(float4*)(rb + 4) = *(const float4*)&Bs[kk][tc + 4];
#pragma unroll
            for (int i = 0; i < 8; i++)
#pragma unroll
                for (int j = 0; j < 8; j++)
                    acc[i][j] = fmaf(ra[i], rb[j], acc[i][j]);
        }
        __syncthreads();
    }

#pragma unroll
    for (int i = 0; i < 8; i++) {
        float* Cp = C + (size_t)(bm + tr + i) * N + bn + tc;
#pragma unroll
        for (int j = 0; j < 8; j++)
            Cp[j] = acc[i][j] + bias[bn + tc + j];
    }
}

// ---------------------------------------------------------------------------
// Attention per (batch, head): one CTA per bh pair, 128 threads.
//  - Q/K/V tiles [64][128] fp32 in smem (row pads 129/129/132 vs bank conflicts)
//  - scores [64][64] (pad 65), scale 1/sqrt(2048), causal mask k<=q
//  - softmax along q (column-wise) — faithful to reference axis=-2
//  - out[q][c] = sum_k P[q][k] * V[k][c], written to [B,S,H*hd] layout
// ---------------------------------------------------------------------------
#define QK_PAD 129
#define V_PAD  132
#define P_PAD  65
#define ATTN_SMEM_FLOATS (2 * SEQ * QK_PAD + SEQ * V_PAD + SEQ * P_PAD)
#define ATTN_SMEM_BYTES  (ATTN_SMEM_FLOATS * 4)

__global__ void __launch_bounds__(128)
attn64(const float* __restrict__ qkv, float* __restrict__ att)
{
    extern __shared__ float sm[];
    float* Qs = sm;                          // 64 * 129
    float* Ks = Qs + SEQ * QK_PAD;           // 64 * 129
    float* Vs = Ks + SEQ * QK_PAD;           // 64 * 132
    float* Ps = Vs + SEQ * V_PAD;            // 64 * 65

    const int bh  = blockIdx.x;
    const int b   = bh >> 4;
    const int h   = bh & 15;
    const int tid = threadIdx.x;

    const float* base = qkv + (size_t)b * SEQ * E3 + h * HD;

    // ---- load Q, K, V tiles (2 threads per row, 64 floats each) ----
    {
        const int r  = tid >> 1;
        const int cp = (tid & 1) * 64;
        const float* src = base + (size_t)r * E3 + cp;
        float* dq = Qs + r * QK_PAD + cp;
        float* dk = Ks + r * QK_PAD + cp;
        float* dv = Vs + r * V_PAD  + cp;
#pragma unroll
        for (int i = 0; i < 64; i += 4) {
            float4 q4 = *(const float4*)(src + i);
            float4 k4 = *(const float4*)(src + DMODEL + i);
            float4 v4 = *(const float4*)(src + 2 * DMODEL + i);
            dq[i] = q4.x; dq[i+1] = q4.y; dq[i+2] = q4.z; dq[i+3] = q4.w;
            dk[i] = k4.x; dk[i+1] = k4.y; dk[i+2] = k4.z; dk[i+3] = k4.w;
            *(float4*)(dv + i) = v4;   // V_PAD divisible by 4 -> aligned
        }
    }
    __syncthreads();

    // ---- scores: thread computes 4q x 8k ----
    {
        const int tq = (tid >> 3) * 4;   // 0..60
        const int tk = (tid & 7) * 8;    // 0..56
        float acc[4][8];
#pragma unroll
        for (int i = 0; i < 4; i++)
#pragma unroll
            for (int j = 0; j < 8; j++) acc[i][j] = 0.0f;

        for (int kd = 0; kd < HD; kd++) {
            float qv[4], kv[8];
#pragma unroll
            for (int i = 0; i < 4; i++) qv[i] = Qs[(tq + i) * QK_PAD + kd];
#pragma unroll
            for (int j = 0; j < 8; j++) kv[j] = Ks[(tk + j) * QK_PAD + kd];
#pragma unroll
            for (int i = 0; i < 4; i++)
#pragma unroll
                for (int j = 0; j < 8; j++)
                    acc[i][j] = fmaf(qv[i], kv[j], acc[i][j]);
        }

        const float scale = 0.022097086912079608f;  // 1/sqrt(2048)
#pragma unroll
        for (int i = 0; i < 4; i++) {
            const int q = tq + i;
#pragma unroll
            for (int j = 0; j < 8; j++) {
                const int k = tk + j;
                Ps[q * P_PAD + k] = (k <= q) ? acc[i][j] * scale : -1e30f;
            }
        }
    }
    __syncthreads();

    // ---- column softmax over q (valid q in [k, 63]) ----
    if (tid < SEQ) {
        const int k = tid;
        float m = -1e30f;
        for (int q = k; q < SEQ; q++) m = fmaxf(m, Ps[q * P_PAD + k]);
        float ssum = 0.0f;
        for (int q = k; q < SEQ; q++) {
            float e = __expf(Ps[q * P_PAD + k] - m);
            Ps[q * P_PAD + k] = e;
            ssum += e;
        }
        const float inv = 1.0f / ssum;
        for (int q = 0; q < SEQ; q++)
            Ps[q * P_PAD + k] = (q < k) ? 0.0f : Ps[q * P_PAD + k] * inv;
    }
    __syncthreads();

    // ---- PV: thread computes 8q x 8c ----
    {
        const int tq = (tid >> 4) * 8;   // 0..56
        const int tc = (tid & 15) * 8;   // 0..120
        float acc[8][8];
#pragma unroll
        for (int i = 0; i < 8; i++)
#pragma unroll
            for (int j = 0; j < 8; j++) acc[i][j] = 0.0f;

        for (int k = 0; k < SEQ; k++) {
            float pv[8], vv[8];
#pragma unroll
            for (int i = 0; i < 8; i++) pv[i] = Ps[(tq + i) * P_PAD + k];
            *(float4*)(vv)     = *(const float4*)&Vs[k * V_PAD + tc];
            *(float4*)(vv + 4) = *(const float4*)&Vs[k * V_PAD + tc + 4];
#pragma unroll
            for (int i = 0; i < 8; i++)
#pragma unroll
                for (int j = 0; j < 8; j++)
                    acc[i][j] = fmaf(pv[i], vv[j], acc[i][j]);
        }

        // write to att[b, q, h*128 + c]  (i.e. [B,S,D] layout)
        float* outp = att + (size_t)b * SEQ * DMODEL + h * HD;
#pragma unroll
        for (int i = 0; i < 8; i++) {
#pragma unroll
            for (int j = 0; j < 8; j++)
                outp[(size_t)(tq + i) * DMODEL + tc + j] = acc[i][j];
        }
    }
}

// ---------------------------------------------------------------------------
// Launch
// ---------------------------------------------------------------------------
extern "C" void kernel_launch(void* const* d_in, const int* in_sizes, int n_in,
                              void* d_out, int out_size)
{
    const float* x     = (const float*)d_in[0];
    const float* W_qkv = (const float*)d_in[1];
    const float* b_qkv = (const float*)d_in[2];
    const float* W_out = (const float*)d_in[3];
    const float* b_out = (const float*)d_in[4];
    float* out = (float*)d_out;

    float* qkv = nullptr;
    float* att = nullptr;
    cudaGetSymbolAddress((void**)&qkv, g_qkv);
    cudaGetSymbolAddress((void**)&att, g_att);

    cudaFuncSetAttribute(attn64, cudaFuncAttributeMaxDynamicSharedMemorySize,
                         ATTN_SMEM_BYTES);

    // 1) qkv = x @ W_qkv^T + b_qkv      [16384, 6144]
    {
        dim3 grid(E3 / 128, TOK / 128);
        gemm_nt<<<grid, 256>>>(x, W_qkv, b_qkv, qkv, TOK, E3, DMODEL);
    }

    // 2) attention per (b, h)
    {
        attn64<<<NBATCH * NHEAD, 128, ATTN_SMEM_BYTES>>>(qkv, att);
    }

    // 3) out = att @ W_out^T + b_out    [16384, 2048]
    {
        dim3 grid(DMODEL / 128, TOK / 128);
        gemm_nt<<<grid, 256>>>(att, W_out, b_out, out, TOK, DMODEL, DMODEL);
    }
}

// round 3
// speedup vs baseline: 1.0002x; 1.0002x over previous
#include <cuda_runtime.h>
#include <cuda_bf16.h>
#include <math.h>

// ---------------------------------------------------------------------------
// Problem constants
//   x      [256, 64, 2048]  fp32
//   W_qkv  [6144, 2048]     fp32   (qkv = x @ W_qkv^T + b_qkv)
//   b_qkv  [6144]
//   W_out  [2048, 2048]     fp32   (out = att @ W_out^T + b_out)
//   b_out  [2048]
//   H = 16 heads, hd = 128, S = 64, B = 256, tokens = 16384
//   scores scaled by 1/sqrt(d_model) = 1/sqrt(2048)
//   softmax over the QUERY axis (axis=-2) per key column, causal mask k<=q
// ---------------------------------------------------------------------------

#define TOK      16384
#define DMODEL   2048
#define E3       6144
#define NHEAD    16
#define HD       128
#define SEQ      64
#define NBATCH   256

// Scratch (device globals: allocation rules forbid cudaMalloc)
__device__ float g_qkv[(size_t)TOK * E3];     // 402 MB
__device__ float g_att[(size_t)TOK * DMODEL]; // 134 MB

// ---------------------------------------------------------------------------
// NT SGEMM: C[M,N] = A[M,K] @ B[N,K]^T + bias[N]
// A row-major [M,K], B row-major [N,K] (both K-contiguous).
// 128x128 tile, BK=8, 256 threads, 8x8 per-thread microtile.
// ---------------------------------------------------------------------------
__global__ void __launch_bounds__(256, 2)
gemm_nt(const float* __restrict__ A, const float* __restrict__ Bm,
        const float* __restrict__ bias, float* __restrict__ C,
        int M, int N, int K)
{
    __shared__ float As[8][128];
    __shared__ float Bs[8][128];

    const int bm  = blockIdx.y * 128;
    const int bn  = blockIdx.x * 128;
    const int tid = threadIdx.x;

    // gmem load mapping: each thread loads one float4 of A and one of B per k-tile
    const int lr = tid >> 1;          // row within tile: 0..127
    const int lk = (tid & 1) * 4;     // k offset: 0 or 4
    const float* Ag = A  + (size_t)(bm + lr) * K + lk;
    const float* Bg = Bm + (size_t)(bn + lr) * K + lk;

    // compute mapping: 16x16 thread grid, 8x8 micro tile
    const int tr = (tid >> 4) * 8;
    const int tc = (tid & 15) * 8;

    float acc[8][8];
#pragma unroll
    for (int i = 0; i < 8; i++)
#pragma unroll
        for (int j = 0; j < 8; j++) acc[i][j] = 0.0f;

    for (int k0 = 0; k0 < K; k0 += 8) {
        float4 a = *(const float4*)(Ag + k0);
        float4 b = *(const float4*)(Bg + k0);
        As[lk + 0][lr] = a.x; As[lk + 1][lr] = a.y;
        As[lk + 2][lr] = a.z; As[lk + 3][lr] = a.w;
        Bs[lk + 0][lr] = b.x; Bs[lk + 1][lr] = b.y;
        Bs[lk + 2][lr] = b.z; Bs[lk + 3][lr] = b.w;
        __syncthreads();

#pragma unroll
        for (int kk = 0; kk < 8; kk++) {
            float ra[8], rb[8];
            *(float4*)(ra)     = *(const float4*)&As[kk][tr];
            *(float4*)(ra + 4) = *(const float4*)&As[kk][tr + 4];
            *(float4*)(rb)     = *(const float4*)&Bs[kk][tc];
            *(float4*)(rb + 4) = *(const float4*)&Bs[kk][tc + 4];
#pragma unroll
            for (int i = 0; i < 8; i++)
#pragma unroll
                for (int j = 0; j < 8; j++)
                    acc[i][j] = fmaf(ra[i], rb[j], acc[i][j]);
        }
        __syncthreads();
    }

#pragma unroll
    for (int i = 0; i < 8; i++) {
        float* Cp = C + (size_t)(bm + tr + i) * N + bn + tc;
#pragma unroll
        for (int j = 0; j < 8; j++)
            Cp[j] = acc[i][j] + bias[bn + tc + j];
    }
}

// ---------------------------------------------------------------------------
// Attention per (batch, head): one CTA per bh pair, 128 threads.
//  - Q/K/V tiles [64][128] fp32 in smem (row pads 129/129/132 vs bank conflicts)
//  - scores [64][64] (pad 65), scale 1/sqrt(2048), causal mask k<=q
//  - softmax along q (column-wise) — faithful to reference axis=-2
//  - out[q][c] = sum_k P[q][k] * V[k][c], written to [B,S,H*hd] layout
// ---------------------------------------------------------------------------
#define QK_PAD 129
#define V_PAD  132
#define P_PAD  65
#define ATTN_SMEM_FLOATS (2 * SEQ * QK_PAD + SEQ * V_PAD + SEQ * P_PAD)
#define ATTN_SMEM_BYTES  (ATTN_SMEM_FLOATS * 4)

__global__ void __launch_bounds__(128)
attn64(const float* __restrict__ qkv, float* __restrict__ att)
{
    extern __shared__ float sm[];
    float* Qs = sm;                          // 64 * 129
    float* Ks = Qs + SEQ * QK_PAD;           // 64 * 129
    float* Vs = Ks + SEQ * QK_PAD;           // 64 * 132
    float* Ps = Vs + SEQ * V_PAD;            // 64 * 65

    const int bh  = blockIdx.x;
    const int b   = bh >> 4;
    const int h   = bh & 15;
    const int tid = threadIdx.x;

    const float* base = qkv + (size_t)b * SEQ * E3 + h * HD;

    // ---- load Q, K, V tiles (2 threads per row, 64 floats each) ----
    {
        const int r  = tid >> 1;
        const int cp = (tid & 1) * 64;
        const float* src = base + (size_t)r * E3 + cp;
        float* dq = Qs + r * QK_PAD + cp;
        float* dk = Ks + r * QK_PAD + cp;
        float* dv = Vs + r * V_PAD  + cp;
#pragma unroll
        for (int i = 0; i < 64; i += 4) {
            float4 q4 = *(const float4*)(src + i);
            float4 k4 = *(const float4*)(src + DMODEL + i);
            float4 v4 = *(const float4*)(src + 2 * DMODEL + i);
            dq[i] = q4.x; dq[i+1] = q4.y; dq[i+2] = q4.z; dq[i+3] = q4.w;
            dk[i] = k4.x; dk[i+1] = k4.y; dk[i+2] = k4.z; dk[i+3] = k4.w;
            *(float4*)(dv + i) = v4;   // V_PAD divisible by 4 -> aligned
        }
    }
    __syncthreads();

    // ---- scores: thread computes 4q x 8k ----
    {
        const int tq = (tid >> 3) * 4;   // 0..60
        const int tk = (tid & 7) * 8;    // 0..56
        float acc[4][8];
#pragma unroll
        for (int i = 0; i < 4; i++)
#pragma unroll
            for (int j = 0; j < 8; j++) acc[i][j] = 0.0f;

        for (int kd = 0; kd < HD; kd++) {
            float qv[4], kv[8];
#pragma unroll
            for (int i = 0; i < 4; i++) qv[i] = Qs[(tq + i) * QK_PAD + kd];
#pragma unroll
            for (int j = 0; j < 8; j++) kv[j] = Ks[(tk + j) * QK_PAD + kd];
#pragma unroll
            for (int i = 0; i < 4; i++)
#pragma unroll
                for (int j = 0; j < 8; j++)
                    acc[i][j] = fmaf(qv[i], kv[j], acc[i][j]);
        }

        const float scale = 0.022097086912079608f;  // 1/sqrt(2048)
#pragma unroll
        for (int i = 0; i < 4; i++) {
            const int q = tq + i;
#pragma unroll
            for (int j = 0; j < 8; j++) {
                const int k = tk + j;
                Ps[q * P_PAD + k] = (k <= q) ? acc[i][j] * scale : -1e30f;
            }
        }
    }
    __syncthreads();

    // ---- column softmax over q (valid q in [k, 63]) ----
    if (tid < SEQ) {
        const int k = tid;
        float m = -1e30f;
        for (int q = k; q < SEQ; q++) m = fmaxf(m, Ps[q * P_PAD + k]);
        float ssum = 0.0f;
        for (int q = k; q < SEQ; q++) {
            float e = __expf(Ps[q * P_PAD + k] - m);
            Ps[q * P_PAD + k] = e;
            ssum += e;
        }
        const float inv = 1.0f / ssum;
        for (int q = 0; q < SEQ; q++)
            Ps[q * P_PAD + k] = (q < k) ? 0.0f : Ps[q * P_PAD + k] * inv;
    }
    __syncthreads();

    // ---- PV: thread computes 8q x 8c ----
    {
        const int tq = (tid >> 4) * 8;   // 0..56
        const int tc = (tid & 15) * 8;   // 0..120
        float acc[8][8];
#pragma unroll
        for (int i = 0; i < 8; i++)
#pragma unroll
            for (int j = 0; j < 8; j++) acc[i][j] = 0.0f;

        for (int k = 0; k < SEQ; k++) {
            float pv[8], vv[8];
#pragma unroll
            for (int i = 0; i < 8; i++) pv[i] = Ps[(tq + i) * P_PAD + k];
            *(float4*)(vv)     = *(const float4*)&Vs[k * V_PAD + tc];
            *(float4*)(vv + 4) = *(const float4*)&Vs[k * V_PAD + tc + 4];
#pragma unroll
            for (int i = 0; i < 8; i++)
#pragma unroll
                for (int j = 0; j < 8; j++)
                    acc[i][j] = fmaf(pv[i], vv[j], acc[i][j]);
        }

        // write to att[b, q, h*128 + c]  (i.e. [B,S,D] layout)
        float* outp = att + (size_t)b * SEQ * DMODEL + h * HD;
#pragma unroll
        for (int i = 0; i < 8; i++) {
#pragma unroll
            for (int j = 0; j < 8; j++)
                outp[(size_t)(tq + i) * DMODEL + tc + j] = acc[i][j];
        }
    }
}

// ---------------------------------------------------------------------------
// Launch
// ---------------------------------------------------------------------------
extern "C" void kernel_launch(void* const* d_in, const int* in_sizes, int n_in,
                              void* d_out, int out_size)
{
    const float* x     = (const float*)d_in[0];
    const float* W_qkv = (const float*)d_in[1];
    const float* b_qkv = (const float*)d_in[2];
    const float* W_out = (const float*)d_in[3];
    const float* b_out = (const float*)d_in[4];
    float* out = (float*)d_out;

    float* qkv = nullptr;
    float* att = nullptr;
    cudaGetSymbolAddress((void**)&qkv, g_qkv);
    cudaGetSymbolAddress((void**)&att, g_att);

    cudaFuncSetAttribute(attn64, cudaFuncAttributeMaxDynamicSharedMemorySize,
                         ATTN_SMEM_BYTES);

    // 1) qkv = x @ W_qkv^T + b_qkv      [16384, 6144]
    {
        dim3 grid(E3 / 128, TOK / 128);
        gemm_nt<<<grid, 256>>>(x, W_qkv, b_qkv, qkv, TOK, E3, DMODEL);
    }

    // 2) attention per (b, h)
    {
        attn64<<<NBATCH * NHEAD, 128, ATTN_SMEM_BYTES>>>(qkv, att);
    }

    // 3) out = att @ W_out^T + b_out    [16384, 2048]
    {
        dim3 grid(DMODEL / 128, TOK / 128);
        gemm_nt<<<grid, 256>>>(att, W_out, b_out, out, TOK, DMODEL, DMODEL);
    }
}

// round 4
// speedup vs baseline: 2.6177x; 2.6172x over previous
#include <cuda_runtime.h>
#include <cuda_bf16.h>
#include <stdint.h>
#include <math.h>

// ---------------------------------------------------------------------------
// Problem constants
//   x      [256, 64, 2048]  fp32
//   W_qkv  [6144, 2048]     fp32   (qkv = x @ W_qkv^T + b_qkv)
//   W_out  [2048, 2048]     fp32   (out = att @ W_out^T + b_out)
//   H=16 heads, hd=128, S=64, B=256, tokens=16384
//   scores scaled by 1/sqrt(2048); softmax over QUERY axis (axis=-2), causal
// ---------------------------------------------------------------------------

#define TOK      16384
#define DMODEL   2048
#define E3       6144
#define NHEAD    16
#define HD       128
#define SEQ      64
#define NBATCH   256

// Scratch (device globals: allocation rules forbid cudaMalloc)
__device__ float g_qkv[(size_t)TOK * E3];        // 402 MB  fp32 qkv
__device__ float g_att[(size_t)TOK * DMODEL];    // 134 MB  attention out (tf32-rounded)
__device__ float g_xr [(size_t)TOK * DMODEL];    // 134 MB  x rounded to tf32
__device__ float g_wqr[(size_t)E3  * DMODEL];    //  50 MB  W_qkv rounded
__device__ float g_wor[(size_t)DMODEL * DMODEL]; //  17 MB  W_out rounded

// ---------------------------------------------------------------------------
// TF32 helpers
// ---------------------------------------------------------------------------
__device__ __forceinline__ float round_tf32(float x) {
    uint32_t u;
    asm("cvt.rna.tf32.f32 %0, %1;" : "=r"(u) : "f"(x));
    return __uint_as_float(u);
}

__global__ void __launch_bounds__(256)
round_tf32_kernel(const float4* __restrict__ in, float4* __restrict__ out, int n4)
{
    int i = blockIdx.x * blockDim.x + threadIdx.x;
    if (i < n4) {
        float4 v = in[i];
        v.x = round_tf32(v.x);
        v.y = round_tf32(v.y);
        v.z = round_tf32(v.z);
        v.w = round_tf32(v.w);
        out[i] = v;
    }
}

// ---------------------------------------------------------------------------
// TF32 tensor-core NT GEMM: C[M,N] = A[M,K] @ B[N,K]^T + bias[N]
// CTA tile 128x128, BK=16, 3-stage cp.async pipeline, 256 threads (8 warps).
// Warp grid 2(m) x 4(n); warp tile 64x32 -> 4 m-atoms x 4 n-atoms of m16n8k8.
// Smem tiles [row][LDK=20] (pad 4) -> conflict-free ldmatrix.
// Inputs must already be tf32-rounded (rna) fp32 values.
// ---------------------------------------------------------------------------
#define BM 128
#define BN 128
#define BK 16
#define STAGES 3
#define LDK 20
#define STAGE_BYTES (BM * LDK * 4)                  // 10240
#define GEMM_SMEM   (STAGES * STAGE_BYTES * 2)      // 61440

__device__ __forceinline__ void cp16(uint32_t dst, const float* src) {
    asm volatile("cp.async.cg.shared.global [%0], [%1], 16;\n" :: "r"(dst), "l"(src));
}
__device__ __forceinline__ void cp_commit() {
    asm volatile("cp.async.commit_group;\n");
}
__device__ __forceinline__ void ldsm4(uint32_t (&r)[4], uint32_t addr) {
    asm volatile("ldmatrix.sync.aligned.m8n8.x4.shared.b16 {%0,%1,%2,%3}, [%4];\n"
                 : "=r"(r[0]), "=r"(r[1]), "=r"(r[2]), "=r"(r[3]) : "r"(addr));
}
__device__ __forceinline__ void mma_tf32(float (&c)[4], const uint32_t (&a)[4],
                                         uint32_t b0, uint32_t b1) {
    asm volatile(
        "mma.sync.aligned.m16n8k8.row.col.f32.tf32.tf32.f32 "
        "{%0,%1,%2,%3},{%4,%5,%6,%7},{%8,%9},{%0,%1,%2,%3};\n"
        : "+f"(c[0]), "+f"(c[1]), "+f"(c[2]), "+f"(c[3])
        : "r"(a[0]), "r"(a[1]), "r"(a[2]), "r"(a[3]), "r"(b0), "r"(b1));
}

__global__ void __launch_bounds__(256, 2)
gemm_nt_tc(const float* __restrict__ A, const float* __restrict__ Bm,
           const float* __restrict__ bias, float* __restrict__ C,
           int M, int N, int K)
{
    extern __shared__ float sm[];
    float* As = sm;
    float* Bs = sm + STAGES * BM * LDK;

    const int tid  = threadIdx.x;
    const int bm   = blockIdx.y * BM;
    const int bn   = blockIdx.x * BN;
    const int warp = tid >> 5;
    const int lane = tid & 31;
    const int wm   = warp >> 2;   // 0..1
    const int wn   = warp & 3;    // 0..3

    const uint32_t smA = (uint32_t)__cvta_generic_to_shared(As);
    const uint32_t smB = (uint32_t)__cvta_generic_to_shared(Bs);

    // gmem->smem mapping: 512 float4 per tile per stage; 2 for A + 2 for B per thread
    const int i0 = tid * 2, i1 = tid * 2 + 1;
    const int ra0 = i0 >> 2, ka0 = (i0 & 3) << 2;
    const int ra1 = i1 >> 2, ka1 = (i1 & 3) << 2;
    const float* Ag0 = A  + (size_t)(bm + ra0) * K + ka0;
    const float* Ag1 = A  + (size_t)(bm + ra1) * K + ka1;
    const float* Bg0 = Bm + (size_t)(bn + ra0) * K + ka0;
    const float* Bg1 = Bm + (size_t)(bn + ra1) * K + ka1;
    const uint32_t sA0 = smA + (uint32_t)((ra0 * LDK + ka0) * 4);
    const uint32_t sA1 = smA + (uint32_t)((ra1 * LDK + ka1) * 4);
    const uint32_t sB0 = smB + (uint32_t)((ra0 * LDK + ka0) * 4);
    const uint32_t sB1 = smB + (uint32_t)((ra1 * LDK + ka1) * 4);

    // ldmatrix per-lane fragment base (lanes 0-15: rows 0..15 @k, 16-31: rows @k+4)
    const int lrow = lane & 15;
    const int lk   = (lane >> 4) << 2;
    const uint32_t aFrag = smA + (uint32_t)(((wm * 64 + lrow) * LDK + lk) * 4);
    const uint32_t bFrag = smB + (uint32_t)(((wn * 32 + lrow) * LDK + lk) * 4);

    float c[4][4][4];
#pragma unroll
    for (int i = 0; i < 4; i++)
#pragma unroll
        for (int j = 0; j < 4; j++)
#pragma unroll
            for (int r = 0; r < 4; r++) c[i][j][r] = 0.0f;

    const int NT = K / BK;

    // prologue: stages 0..STAGES-2
#pragma unroll
    for (int p = 0; p < STAGES - 1; p++) {
        const int koff = p * BK;
        const uint32_t so = (uint32_t)(p * STAGE_BYTES);
        cp16(sA0 + so, Ag0 + koff);
        cp16(sA1 + so, Ag1 + koff);
        cp16(sB0 + so, Bg0 + koff);
        cp16(sB1 + so, Bg1 + koff);
        cp_commit();
    }

    int st = 0;
    for (int s = 0; s < NT; s++) {
        if (s + 2 < NT) {
            asm volatile("cp.async.wait_group 1;\n");
        } else {
            asm volatile("cp.async.wait_group 0;\n");
        }
        __syncthreads();

        // compute stage st
        {
            const uint32_t aOff = aFrag + (uint32_t)(st * STAGE_BYTES);
            const uint32_t bOff = bFrag + (uint32_t)(st * STAGE_BYTES);
#pragma unroll
            for (int ks = 0; ks < 2; ks++) {
                uint32_t a[4][4];
#pragma unroll
                for (int am = 0; am < 4; am++)
                    ldsm4(a[am], aOff + ks * 32 + am * (16 * LDK * 4));
                uint32_t b[2][4];
#pragma unroll
                for (int pr = 0; pr < 2; pr++)
                    ldsm4(b[pr], bOff + ks * 32 + pr * (16 * LDK * 4));
#pragma unroll
                for (int am = 0; am < 4; am++)
#pragma unroll
                    for (int an = 0; an < 4; an++)
                        mma_tf32(c[am][an], a[am], b[an >> 1][an & 1], b[an >> 1][2 + (an & 1)]);
            }
        }
        __syncthreads();

        // prefetch stage s + STAGES - 1 into buffer just consumed... (st is free after sync)
        if (s + STAGES - 1 < NT) {
            const int koff = (s + STAGES - 1) * BK;
            const uint32_t so = (uint32_t)(((s + STAGES - 1) % STAGES) * STAGE_BYTES);
            cp16(sA0 + so, Ag0 + koff);
            cp16(sA1 + so, Ag1 + koff);
            cp16(sB0 + so, Bg0 + koff);
            cp16(sB1 + so, Bg1 + koff);
            cp_commit();
        }
        st = (st + 1 == STAGES) ? 0 : st + 1;
    }

    // epilogue: c0,c1 -> (row, col..col+1), c2,c3 -> (row+8, ...)
    const int erow = lane >> 2;
    const int ecol = (lane & 3) * 2;
#pragma unroll
    for (int am = 0; am < 4; am++) {
        const int row = bm + wm * 64 + am * 16 + erow;
#pragma unroll
        for (int an = 0; an < 4; an++) {
            const int col = bn + wn * 32 + an * 8 + ecol;
            const float b0v = __ldg(bias + col);
            const float b1v = __ldg(bias + col + 1);
            float* p0 = C + (size_t)row * N + col;
            float* p1 = C + (size_t)(row + 8) * N + col;
            p0[0] = c[am][an][0] + b0v;
            p0[1] = c[am][an][1] + b1v;
            p1[0] = c[am][an][2] + b0v;
            p1[1] = c[am][an][3] + b1v;
        }
    }
}

// ---------------------------------------------------------------------------
// Attention per (batch, head): one CTA per bh pair, 128 threads. fp32 SIMT.
// Output rounded to tf32 (rna) so GEMM3 consumes unbiased tf32 operands.
// ---------------------------------------------------------------------------
#define QK_PAD 129
#define V_PAD  132
#define P_PAD  65
#define ATTN_SMEM_FLOATS (2 * SEQ * QK_PAD + SEQ * V_PAD + SEQ * P_PAD)
#define ATTN_SMEM_BYTES  (ATTN_SMEM_FLOATS * 4)

__global__ void __launch_bounds__(128)
attn64(const float* __restrict__ qkv, float* __restrict__ att)
{
    extern __shared__ float smn[];
    float* Qs = smn;
    float* Ks = Qs + SEQ * QK_PAD;
    float* Vs = Ks + SEQ * QK_PAD;
    float* Ps = Vs + SEQ * V_PAD;

    const int bh  = blockIdx.x;
    const int b   = bh >> 4;
    const int h   = bh & 15;
    const int tid = threadIdx.x;

    const float* base = qkv + (size_t)b * SEQ * E3 + h * HD;

    {
        const int r  = tid >> 1;
        const int cp = (tid & 1) * 64;
        const float* src = base + (size_t)r * E3 + cp;
        float* dq = Qs + r * QK_PAD + cp;
        float* dk = Ks + r * QK_PAD + cp;
        float* dv = Vs + r * V_PAD  + cp;
#pragma unroll
        for (int i = 0; i < 64; i += 4) {
            float4 q4 = *(const float4*)(src + i);
            float4 k4 = *(const float4*)(src + DMODEL + i);
            float4 v4 = *(const float4*)(src + 2 * DMODEL + i);
            dq[i] = q4.x; dq[i+1] = q4.y; dq[i+2] = q4.z; dq[i+3] = q4.w;
            dk[i] = k4.x; dk[i+1] = k4.y; dk[i+2] = k4.z; dk[i+3] = k4.w;
            *(float4*)(dv + i) = v4;
        }
    }
    __syncthreads();

    {
        const int tq = (tid >> 3) * 4;
        const int tk = (tid & 7) * 8;
        float acc[4][8];
#pragma unroll
        for (int i = 0; i < 4; i++)
#pragma unroll
            for (int j = 0; j < 8; j++) acc[i][j] = 0.0f;

        for (int kd = 0; kd < HD; kd++) {
            float qv[4], kv[8];
#pragma unroll
            for (int i = 0; i < 4; i++) qv[i] = Qs[(tq + i) * QK_PAD + kd];
#pragma unroll
            for (int j = 0; j < 8; j++) kv[j] = Ks[(tk + j) * QK_PAD + kd];
#pragma unroll
            for (int i = 0; i < 4; i++)
#pragma unroll
                for (int j = 0; j < 8; j++)
                    acc[i][j] = fmaf(qv[i], kv[j], acc[i][j]);
        }

        const float scale = 0.022097086912079608f;  // 1/sqrt(2048)
#pragma unroll
        for (int i = 0; i < 4; i++) {
            const int q = tq + i;
#pragma unroll
            for (int j = 0; j < 8; j++) {
                const int k = tk + j;
                Ps[q * P_PAD + k] = (k <= q) ? acc[i][j] * scale : -1e30f;
            }
        }
    }
    __syncthreads();

    if (tid < SEQ) {
        const int k = tid;
        float m = -1e30f;
        for (int q = k; q < SEQ; q++) m = fmaxf(m, Ps[q * P_PAD + k]);
        float ssum = 0.0f;
        for (int q = k; q < SEQ; q++) {
            float e = __expf(Ps[q * P_PAD + k] - m);
            Ps[q * P_PAD + k] = e;
            ssum += e;
        }
        const float inv = 1.0f / ssum;
        for (int q = 0; q < SEQ; q++)
            Ps[q * P_PAD + k] = (q < k) ? 0.0f : Ps[q * P_PAD + k] * inv;
    }
    __syncthreads();

    {
        const int tq = (tid >> 4) * 8;
        const int tc = (tid & 15) * 8;
        float acc[8][8];
#pragma unroll
        for (int i = 0; i < 8; i++)
#pragma unroll
            for (int j = 0; j < 8; j++) acc[i][j] = 0.0f;

        for (int k = 0; k < SEQ; k++) {
            float pv[8], vv[8];
#pragma unroll
            for (int i = 0; i < 8; i++) pv[i] = Ps[(tq + i) * P_PAD + k];
            *(float4*)(vv)     = *(const float4*)&Vs[k * V_PAD + tc];
            *(float4*)(vv + 4) = *(const float4*)&Vs[k * V_PAD + tc + 4];
#pragma unroll
            for (int i = 0; i < 8; i++)
#pragma unroll
                for (int j = 0; j < 8; j++)
                    acc[i][j] = fmaf(pv[i], vv[j], acc[i][j]);
        }

        float* outp = att + (size_t)b * SEQ * DMODEL + h * HD;
#pragma unroll
        for (int i = 0; i < 8; i++)
#pragma unroll
            for (int j = 0; j < 8; j++)
                outp[(size_t)(tq + i) * DMODEL + tc + j] = round_tf32(acc[i][j]);
    }
}

// ---------------------------------------------------------------------------
// Launch
// ---------------------------------------------------------------------------
extern "C" void kernel_launch(void* const* d_in, const int* in_sizes, int n_in,
                              void* d_out, int out_size)
{
    const float* x     = (const float*)d_in[0];
    const float* W_qkv = (const float*)d_in[1];
    const float* b_qkv = (const float*)d_in[2];
    const float* W_out = (const float*)d_in[3];
    const float* b_out = (const float*)d_in[4];
    float* out = (float*)d_out;

    float *qkv = nullptr, *att = nullptr, *xr = nullptr, *wqr = nullptr, *wor = nullptr;
    cudaGetSymbolAddress((void**)&qkv, g_qkv);
    cudaGetSymbolAddress((void**)&att, g_att);
    cudaGetSymbolAddress((void**)&xr,  g_xr);
    cudaGetSymbolAddress((void**)&wqr, g_wqr);
    cudaGetSymbolAddress((void**)&wor, g_wor);

    cudaFuncSetAttribute(gemm_nt_tc, cudaFuncAttributeMaxDynamicSharedMemorySize, GEMM_SMEM);
    cudaFuncSetAttribute(attn64, cudaFuncAttributeMaxDynamicSharedMemorySize, ATTN_SMEM_BYTES);

    // 0) unbiased tf32 rounding of GEMM inputs (HMMA truncates raw fp32 -> biased)
    {
        int n4x = TOK * DMODEL / 4;
        round_tf32_kernel<<<n4x / 256, 256>>>((const float4*)x, (float4*)xr, n4x);
        int n4q = E3 * DMODEL / 4;
        round_tf32_kernel<<<n4q / 256, 256>>>((const float4*)W_qkv, (float4*)wqr, n4q);
        int n4o = DMODEL * DMODEL / 4;
        round_tf32_kernel<<<n4o / 256, 256>>>((const float4*)W_out, (float4*)wor, n4o);
    }

    // 1) qkv = x @ W_qkv^T + b_qkv   [16384, 6144]
    {
        dim3 grid(E3 / BN, TOK / BM);
        gemm_nt_tc<<<grid, 256, GEMM_SMEM>>>(xr, wqr, b_qkv, qkv, TOK, E3, DMODEL);
    }

    // 2) attention per (b, h) — fp32, writes tf32-rounded output
    {
        attn64<<<NBATCH * NHEAD, 128, ATTN_SMEM_BYTES>>>(qkv, att);
    }

    // 3) out = att @ W_out^T + b_out  [16384, 2048]
    {
        dim3 grid(DMODEL / BN, TOK / BM);
        gemm_nt_tc<<<grid, 256, GEMM_SMEM>>>(att, wor, b_out, out, TOK, DMODEL, DMODEL);
    }
}

// round 7
// speedup vs baseline: 3.3509x; 1.2801x over previous
#include <cuda_runtime.h>
#include <cuda_bf16.h>
#include <stdint.h>
#include <math.h>

// ---------------------------------------------------------------------------
// Problem constants
// ---------------------------------------------------------------------------
#define TOK      16384
#define DMODEL   2048
#define E3       6144
#define NHEAD    16
#define HD       128
#define SEQ      64
#define NBATCH   256

// Scratch (device globals: allocation rules forbid cudaMalloc)
__device__ float g_qkv[(size_t)TOK * E3];
__device__ float g_att[(size_t)TOK * DMODEL];
__device__ float g_xr [(size_t)TOK * DMODEL];
__device__ float g_wqr[(size_t)E3  * DMODEL];
__device__ float g_wor[(size_t)DMODEL * DMODEL];

// ---------------------------------------------------------------------------
// TF32 helpers
// ---------------------------------------------------------------------------
__device__ __forceinline__ float round_tf32(float x) {
    uint32_t u;
    asm("cvt.rna.tf32.f32 %0, %1;" : "=r"(u) : "f"(x));
    return __uint_as_float(u);
}

__global__ void __launch_bounds__(256)
round_tf32_kernel(const float4* __restrict__ in, float4* __restrict__ out, int n4)
{
    int i = blockIdx.x * blockDim.x + threadIdx.x;
    if (i < n4) {
        float4 v = in[i];
        v.x = round_tf32(v.x);
        v.y = round_tf32(v.y);
        v.z = round_tf32(v.z);
        v.w = round_tf32(v.w);
        out[i] = v;
    }
}

// ---------------------------------------------------------------------------
// TF32 tensor-core NT GEMM: C[M,N] = A[M,K] @ B[N,K]^T + bias[N]
// CTA tile 128x128, BK=32, 3-stage cp.async pipeline, ONE barrier per k-iter.
// 256 threads (8 warps, 2m x 4n); warp tile 64x32 -> 4x4 m16n8k8 atoms.
// Smem [row][LDK=36] (16B pad): ldmatrix phase banks = (4*row+k)%32, all
// distinct -> conflict-free.
// Inputs must be tf32-pre-rounded (rna); accumulation fp32.
// ---------------------------------------------------------------------------
#define BM 128
#define BN 128
#define BK 32
#define STAGES 3
#define LDK 36
#define STAGE_BYTES (BM * LDK * 4)                  // 18432
#define GEMM_SMEM   (STAGES * STAGE_BYTES * 2)      // 110592

__device__ __forceinline__ void cp16(uint32_t dst, const float* src) {
    asm volatile("cp.async.cg.shared.global [%0], [%1], 16;\n" :: "r"(dst), "l"(src));
}
__device__ __forceinline__ void cp_commit() {
    asm volatile("cp.async.commit_group;\n");
}
__device__ __forceinline__ void ldsm4(uint32_t (&r)[4], uint32_t addr) {
    asm volatile("ldmatrix.sync.aligned.m8n8.x4.shared.b16 {%0,%1,%2,%3}, [%4];\n"
                 : "=r"(r[0]), "=r"(r[1]), "=r"(r[2]), "=r"(r[3]) : "r"(addr));
}
__device__ __forceinline__ void mma_tf32(float (&c)[4], const uint32_t (&a)[4],
                                         uint32_t b0, uint32_t b1) {
    asm volatile(
        "mma.sync.aligned.m16n8k8.row.col.f32.tf32.tf32.f32 "
        "{%0,%1,%2,%3},{%4,%5,%6,%7},{%8,%9},{%0,%1,%2,%3};\n"
        : "+f"(c[0]), "+f"(c[1]), "+f"(c[2]), "+f"(c[3])
        : "r"(a[0]), "r"(a[1]), "r"(a[2]), "r"(a[3]), "r"(b0), "r"(b1));
}

__global__ void __launch_bounds__(256, 2)
gemm_nt_tc(const float* __restrict__ A, const float* __restrict__ Bm,
           const float* __restrict__ bias, float* __restrict__ C,
           int M, int N, int K)
{
    extern __shared__ float sm[];
    float* As = sm;
    float* Bs = sm + STAGES * BM * LDK;

    const int tid  = threadIdx.x;
    const int bm   = blockIdx.y * BM;
    const int bn   = blockIdx.x * BN;
    const int warp = tid >> 5;
    const int lane = tid & 31;
    const int wm   = warp >> 2;   // 0..1
    const int wn   = warp & 3;    // 0..3

    const uint32_t smA = (uint32_t)__cvta_generic_to_shared(As);
    const uint32_t smB = (uint32_t)__cvta_generic_to_shared(Bs);

    // gmem->smem: per stage 1024 float4 for A + 1024 for B; 4+4 per thread
    const float* AgP[4]; const float* BgP[4];
    uint32_t sAP[4], sBP[4];
#pragma unroll
    for (int i = 0; i < 4; i++) {
        const int c   = tid + i * 256;       // 0..1023
        const int row = c >> 3;              // 0..127
        const int f4  = c & 7;               // 0..7  (f4*4 = k offset)
        AgP[i] = A  + (size_t)(bm + row) * K + f4 * 4;
        BgP[i] = Bm + (size_t)(bn + row) * K + f4 * 4;
        sAP[i] = smA + (uint32_t)((row * LDK + f4 * 4) * 4);
        sBP[i] = smB + (uint32_t)((row * LDK + f4 * 4) * 4);
    }

    // ldmatrix per-lane fragment base
    const int lrow = lane & 15;
    const int lk   = (lane >> 4) << 2;
    const uint32_t aFrag = smA + (uint32_t)(((wm * 64 + lrow) * LDK + lk) * 4);
    const uint32_t bFrag = smB + (uint32_t)(((wn * 32 + lrow) * LDK + lk) * 4);

    float c[4][4][4];
#pragma unroll
    for (int i = 0; i < 4; i++)
#pragma unroll
        for (int j = 0; j < 4; j++)
#pragma unroll
            for (int r = 0; r < 4; r++) c[i][j][r] = 0.0f;

    const int NT = K / BK;     // 64 (K=2048) or 64

    // prologue: stages 0..STAGES-2
#pragma unroll
    for (int p = 0; p < STAGES - 1; p++) {
        const int koff = p * BK;
        const uint32_t so = (uint32_t)(p * STAGE_BYTES);
#pragma unroll
        for (int i = 0; i < 4; i++) {
            cp16(sAP[i] + so, AgP[i] + koff);
            cp16(sBP[i] + so, BgP[i] + koff);
        }
        cp_commit();
    }

    int st = 0;
    for (int s = 0; s < NT; s++) {
        // stage s ready when <= (pending-1) groups outstanding
        if (s + 1 < NT) {
            asm volatile("cp.async.wait_group 1;\n");
        } else {
            asm volatile("cp.async.wait_group 0;\n");
        }
        __syncthreads();   // all warps finished stage s-1 compute; slot free

        // prefetch stage s+STAGES-1 into slot (s+STAGES-1)%STAGES == (s-1)%STAGES
        if (s + STAGES - 1 < NT) {
            const int koff = (s + STAGES - 1) * BK;
            const uint32_t so = (uint32_t)(((s + STAGES - 1) % STAGES) * STAGE_BYTES);
#pragma unroll
            for (int i = 0; i < 4; i++) {
                cp16(sAP[i] + so, AgP[i] + koff);
                cp16(sBP[i] + so, BgP[i] + koff);
            }
            cp_commit();
        }

        // compute stage st: 4 k8-steps
        {
            const uint32_t aOff = aFrag + (uint32_t)(st * STAGE_BYTES);
            const uint32_t bOff = bFrag + (uint32_t)(st * STAGE_BYTES);
#pragma unroll
            for (int ks = 0; ks < 4; ks++) {
                uint32_t a[4][4];
#pragma unroll
                for (int am = 0; am < 4; am++)
                    ldsm4(a[am], aOff + ks * 32 + am * (16 * LDK * 4));
                uint32_t b[2][4];
#pragma unroll
                for (int pr = 0; pr < 2; pr++)
                    ldsm4(b[pr], bOff + ks * 32 + pr * (16 * LDK * 4));
#pragma unroll
                for (int am = 0; am < 4; am++)
#pragma unroll
                    for (int an = 0; an < 4; an++)
                        mma_tf32(c[am][an], a[am], b[an >> 1][an & 1], b[an >> 1][2 + (an & 1)]);
            }
        }
        st = (st + 1 == STAGES) ? 0 : st + 1;
    }

    // epilogue
    const int erow = lane >> 2;
    const int ecol = (lane & 3) * 2;
#pragma unroll
    for (int am = 0; am < 4; am++) {
        const int row = bm + wm * 64 + am * 16 + erow;
#pragma unroll
        for (int an = 0; an < 4; an++) {
            const int col = bn + wn * 32 + an * 8 + ecol;
            const float b0v = __ldg(bias + col);
            const float b1v = __ldg(bias + col + 1);
            float* p0 = C + (size_t)row * N + col;
            float* p1 = C + (size_t)(row + 8) * N + col;
            p0[0] = c[am][an][0] + b0v;
            p0[1] = c[am][an][1] + b1v;
            p1[0] = c[am][an][2] + b0v;
            p1[1] = c[am][an][3] + b1v;
        }
    }
}

// ---------------------------------------------------------------------------
// Attention per (batch, head): K/V/P in smem (83KB -> 2 CTA/SM), Q streamed
// from gmem (L1-resident, 8x reuse). fp32; output tf32-rounded for GEMM3.
// ---------------------------------------------------------------------------
#define K_PAD 129
#define V_PAD 132
#define P_PAD 65
#define ATTN_SMEM_FLOATS (SEQ * K_PAD + SEQ * V_PAD + SEQ * P_PAD)
#define ATTN_SMEM_BYTES  (ATTN_SMEM_FLOATS * 4)

__global__ void __launch_bounds__(128)
attn64(const float* __restrict__ qkv, float* __restrict__ att)
{
    extern __shared__ float smn[];
    float* Ks = smn;
    float* Vs = Ks + SEQ * K_PAD;
    float* Ps = Vs + SEQ * V_PAD;

    const int bh  = blockIdx.x;
    const int b   = bh >> 4;
    const int h   = bh & 15;
    const int tid = threadIdx.x;

    const float* base = qkv + (size_t)b * SEQ * E3 + h * HD;

    // load K, V tiles (2 threads per row, 64 floats each)
    {
        const int r  = tid >> 1;
        const int cp = (tid & 1) * 64;
        const float* src = base + (size_t)r * E3 + cp;
        float* dk = Ks + r * K_PAD + cp;
        float* dv = Vs + r * V_PAD + cp;
#pragma unroll
        for (int i = 0; i < 64; i += 4) {
            float4 k4 = *(const float4*)(src + DMODEL + i);
            float4 v4 = *(const float4*)(src + 2 * DMODEL + i);
            dk[i] = k4.x; dk[i+1] = k4.y; dk[i+2] = k4.z; dk[i+3] = k4.w;
            *(float4*)(dv + i) = v4;
        }
    }
    __syncthreads();

    // scores: thread computes 4q x 8k, Q from gmem (L1)
    {
        const int tq = (tid >> 3) * 4;
        const int tk = (tid & 7) * 8;
        const float* q0 = base + (size_t)(tq + 0) * E3;
        const float* q1 = base + (size_t)(tq + 1) * E3;
        const float* q2 = base + (size_t)(tq + 2) * E3;
        const float* q3 = base + (size_t)(tq + 3) * E3;
        float acc[4][8];
#pragma unroll
        for (int i = 0; i < 4; i++)
#pragma unroll
            for (int j = 0; j < 8; j++) acc[i][j] = 0.0f;

        for (int kd = 0; kd < HD; kd += 4) {
            float qv[4][4];
            *(float4*)qv[0] = __ldg((const float4*)(q0 + kd));
            *(float4*)qv[1] = __ldg((const float4*)(q1 + kd));
            *(float4*)qv[2] = __ldg((const float4*)(q2 + kd));
            *(float4*)qv[3] = __ldg((const float4*)(q3 + kd));
#pragma unroll
            for (int kk = 0; kk < 4; kk++) {
                float kv[8];
#pragma unroll
                for (int j = 0; j < 8; j++) kv[j] = Ks[(tk + j) * K_PAD + kd + kk];
#pragma unroll
                for (int i = 0; i < 4; i++)
#pragma unroll
                    for (int j = 0; j < 8; j++)
                        acc[i][j] = fmaf(qv[i][kk], kv[j], acc[i][j]);
            }
        }

        const float scale = 0.022097086912079608f;  // 1/sqrt(2048)
#pragma unroll
        for (int i = 0; i < 4; i++) {
            const int q = tq + i;
#pragma unroll
            for (int j = 0; j < 8; j++) {
                const int k = tk + j;
                Ps[q * P_PAD + k] = (k <= q) ? acc[i][j] * scale : -1e30f;
            }
        }
    }
    __syncthreads();

    // column softmax over q (axis=-2), valid q in [k, 63]
    if (tid < SEQ) {
        const int k = tid;
        float m = -1e30f;
        for (int q = k; q < SEQ; q++) m = fmaxf(m, Ps[q * P_PAD + k]);
        float ssum = 0.0f;
        for (int q = k; q < SEQ; q++) {
            float e = __expf(Ps[q * P_PAD + k] - m);
            Ps[q * P_PAD + k] = e;
            ssum += e;
        }
        const float inv = 1.0f / ssum;
        for (int q = 0; q < SEQ; q++)
            Ps[q * P_PAD + k] = (q < k) ? 0.0f : Ps[q * P_PAD + k] * inv;
    }
    __syncthreads();

    // PV: thread computes 8q x 8c
    {
        const int tq = (tid >> 4) * 8;
        const int tc = (tid & 15) * 8;
        float acc[8][8];
#pragma unroll
        for (int i = 0; i < 8; i++)
#pragma unroll
            for (int j = 0; j < 8; j++) acc[i][j] = 0.0f;

        for (int k = 0; k < SEQ; k++) {
            float pv[8], vv[8];
#pragma unroll
            for (int i = 0; i < 8; i++) pv[i] = Ps[(tq + i) * P_PAD + k];
            *(float4*)(vv)     = *(const float4*)&Vs[k * V_PAD + tc];
            *(float4*)(vv + 4) = *(const float4*)&Vs[k * V_PAD + tc + 4];
#pragma unroll
            for (int i = 0; i < 8; i++)
#pragma unroll
                for (int j = 0; j < 8; j++)
                    acc[i][j] = fmaf(pv[i], vv[j], acc[i][j]);
        }

        float* outp = att + (size_t)b * SEQ * DMODEL + h * HD;
#pragma unroll
        for (int i = 0; i < 8; i++)
#pragma unroll
            for (int j = 0; j < 8; j++)
                outp[(size_t)(tq + i) * DMODEL + tc + j] = round_tf32(acc[i][j]);
    }
}

// ---------------------------------------------------------------------------
// Launch
// ---------------------------------------------------------------------------
extern "C" void kernel_launch(void* const* d_in, const int* in_sizes, int n_in,
                              void* d_out, int out_size)
{
    const float* x     = (const float*)d_in[0];
    const float* W_qkv = (const float*)d_in[1];
    const float* b_qkv = (const float*)d_in[2];
    const float* W_out = (const float*)d_in[3];
    const float* b_out = (const float*)d_in[4];
    float* out = (float*)d_out;

    float *qkv = nullptr, *att = nullptr, *xr = nullptr, *wqr = nullptr, *wor = nullptr;
    cudaGetSymbolAddress((void**)&qkv, g_qkv);
    cudaGetSymbolAddress((void**)&att, g_att);
    cudaGetSymbolAddress((void**)&xr,  g_xr);
    cudaGetSymbolAddress((void**)&wqr, g_wqr);
    cudaGetSymbolAddress((void**)&wor, g_wor);

    cudaFuncSetAttribute(gemm_nt_tc, cudaFuncAttributeMaxDynamicSharedMemorySize, GEMM_SMEM);
    cudaFuncSetAttribute(attn64, cudaFuncAttributeMaxDynamicSharedMemorySize, ATTN_SMEM_BYTES);

    // 0) unbiased tf32 rounding of GEMM inputs
    {
        int n4x = TOK * DMODEL / 4;
        round_tf32_kernel<<<n4x / 256, 256>>>((const float4*)x, (float4*)xr, n4x);
        int n4q = E3 * DMODEL / 4;
        round_tf32_kernel<<<n4q / 256, 256>>>((const float4*)W_qkv, (float4*)wqr, n4q);
        int n4o = DMODEL * DMODEL / 4;
        round_tf32_kernel<<<n4o / 256, 256>>>((const float4*)W_out, (float4*)wor, n4o);
    }

    // 1) qkv = x @ W_qkv^T + b_qkv   [16384, 6144]
    {
        dim3 grid(E3 / BN, TOK / BM);
        gemm_nt_tc<<<grid, 256, GEMM_SMEM>>>(xr, wqr, b_qkv, qkv, TOK, E3, DMODEL);
    }

    // 2) attention per (b, h)
    {
        attn64<<<NBATCH * NHEAD, 128, ATTN_SMEM_BYTES>>>(qkv, att);
    }

    // 3) out = att @ W_out^T + b_out  [16384, 2048]
    {
        dim3 grid(DMODEL / BN, TOK / BM);
        gemm_nt_tc<<<grid, 256, GEMM_SMEM>>>(att, wor, b_out, out, TOK, DMODEL, DMODEL);
    }
}